// round 1
// baseline (speedup 1.0000x reference)
#include <cuda_runtime.h>
#include <cuda_bf16.h>
#include <math.h>

// Problem dims
#define BB 256
#define TT 512
#define DD 256
#define KK 256
#define MM (BB * TT)   // 131072

// ---------------- scratch (device globals: allowed) ----------------
__device__ float g_xu[(size_t)MM * KK];     // 128 MB: x@U + b
__device__ float g_wt4[DD * KK];            // repacked W: [(d/4)][k][d%4]

// ---------------- phase 0: repack W ----------------
// g_wt4[ ((d>>2)*KK + k)*4 + (d&3) ] = W[d*KK + k]
__global__ void prep_w_kernel(const float* __restrict__ W) {
    int i = blockIdx.x * 256 + threadIdx.x;   // 0 .. 65535
    int d = i >> 8;
    int k = i & 255;
    g_wt4[(((d >> 2) * KK + k) << 2) + (d & 3)] = W[i];
}

// ---------------- phase 1: xU = X @ U + b ----------------
// Tiled SGEMM: BM=128, BN=64, BK=16, TM=8, TN=4, 256 threads.
#define P1_BM 128
#define P1_BN 64
#define P1_BK 16

__global__ __launch_bounds__(256) void xu_gemm_kernel(
    const float* __restrict__ X,   // [MM, DD]
    const float* __restrict__ U,   // [DD, KK]
    const float* __restrict__ bias // [KK]
) {
    __shared__ float As[P1_BK][P1_BM];   // A stored transposed
    __shared__ float Bs[P1_BK][P1_BN];

    const int tid = threadIdx.x;
    const int m0 = blockIdx.x * P1_BM;
    const int n0 = blockIdx.y * P1_BN;
    const int tx = tid & 15;   // n dir: 16 * 4 = 64
    const int ty = tid >> 4;   // m dir: 16 * 8 = 128

    float acc[8][4];
#pragma unroll
    for (int i = 0; i < 8; ++i)
#pragma unroll
        for (int j = 0; j < 4; ++j) acc[i][j] = 0.f;

    const int ar = tid >> 2;          // 0..63
    const int ac4 = (tid & 3) << 2;   // 0,4,8,12
    const int br = tid >> 4;          // 0..15
    const int bc4 = (tid & 15) << 2;  // 0..60

    for (int k0 = 0; k0 < DD; k0 += P1_BK) {
        // load A tile 128x16 (2 float4 per thread), store transposed
#pragma unroll
        for (int i = 0; i < 2; ++i) {
            int r = ar + i * 64;
            float4 v = *(const float4*)&X[(size_t)(m0 + r) * DD + k0 + ac4];
            As[ac4 + 0][r] = v.x;
            As[ac4 + 1][r] = v.y;
            As[ac4 + 2][r] = v.z;
            As[ac4 + 3][r] = v.w;
        }
        // load B tile 16x64 (1 float4 per thread)
        {
            float4 v = *(const float4*)&U[(size_t)(k0 + br) * KK + n0 + bc4];
            *(float4*)&Bs[br][bc4] = v;
        }
        __syncthreads();

#pragma unroll
        for (int kk = 0; kk < P1_BK; ++kk) {
            float a[8], b[4];
            *(float4*)&a[0] = *(const float4*)&As[kk][ty * 8 + 0];
            *(float4*)&a[4] = *(const float4*)&As[kk][ty * 8 + 4];
            *(float4*)&b[0] = *(const float4*)&Bs[kk][tx * 4];
#pragma unroll
            for (int i = 0; i < 8; ++i)
#pragma unroll
                for (int j = 0; j < 4; ++j) acc[i][j] += a[i] * b[j];
        }
        __syncthreads();
    }

    // epilogue: add bias, write
    float4 bv = *(const float4*)&bias[n0 + tx * 4];
#pragma unroll
    for (int i = 0; i < 8; ++i) {
        int m = m0 + ty * 8 + i;
        float4 o;
        o.x = acc[i][0] + bv.x;
        o.y = acc[i][1] + bv.y;
        o.z = acc[i][2] + bv.z;
        o.w = acc[i][3] + bv.w;
        *(float4*)&g_xu[(size_t)m * KK + n0 + tx * 4] = o;
    }
}

// ---------------- phase 2: recurrence ----------------
// 128 blocks x 256 threads; each block owns 2 batch rows for all 512 steps.
// W rows d in [0, 4*D4_SMEM) live in SMEM (repacked float4-of-4-d per k);
// remaining rows stream from L2 (hot: same 64KB per step chip-wide).
#define D4_SMEM 48              // 192 of 256 d-rows in smem
#define D4_TOT  64
#define SMEM_W_FLOATS (D4_SMEM * KK * 4)          // 49152 floats = 192KB
#define SMEM_TOTAL_BYTES ((SMEM_W_FLOATS + 2 * 2 * KK) * 4)

__global__ __launch_bounds__(256, 1) void rnn_rec_kernel(float* __restrict__ out) {
    extern __shared__ float smem[];
    float* Ws = smem;                         // [D4_SMEM*KK] float4-groups (flat floats)
    float* hb = smem + SMEM_W_FLOATS;         // h[buf][row][k] : 2*2*256

    const int k = threadIdx.x;
    const int b0 = blockIdx.x * 2;
    const int b1 = b0 + 1;

    // stage W (smem portion) once
    const float4* wt4 = (const float4*)g_wt4;
    float4* ws4 = (float4*)Ws;
    for (int i = k; i < D4_SMEM * KK; i += 256) ws4[i] = wt4[i];

    const float* xu0 = g_xu + (size_t)b0 * TT * KK + k;
    const float* xu1 = g_xu + (size_t)b1 * TT * KK + k;

    // t = 0 : h = tanh(xu_0)
    float a0 = xu0[0];
    float a1 = xu1[0];
    __syncthreads();          // Ws staged, h buffers safe to write
    int cur = 0;
    hb[cur * 512 + 0 * KK + k] = tanhf(a0);
    hb[cur * 512 + 1 * KK + k] = tanhf(a1);
    __syncthreads();

    float r0 = 0.f, r1 = 0.f;
    for (int t = 1; t < TT; ++t) {
        float x0 = xu0[(size_t)t * KK];   // long-latency, consumed at tanh
        float x1 = xu1[(size_t)t * KK];
        const float4* h0 = (const float4*)&hb[cur * 512 + 0 * KK];
        const float4* h1 = (const float4*)&hb[cur * 512 + 1 * KK];
        float s0 = 0.f, s1 = 0.f;

        // smem part of W
#pragma unroll 8
        for (int d4 = 0; d4 < D4_SMEM; ++d4) {
            float4 w = ws4[d4 * KK + k];
            float4 p0 = h0[d4];
            float4 p1 = h1[d4];
            s0 += w.x * p0.x + w.y * p0.y + w.z * p0.z + w.w * p0.w;
            s1 += w.x * p1.x + w.y * p1.y + w.z * p1.z + w.w * p1.w;
        }
        // L2-resident part of W
#pragma unroll
        for (int d4 = D4_SMEM; d4 < D4_TOT; ++d4) {
            float4 w = __ldg(&wt4[d4 * KK + k]);
            float4 p0 = h0[d4];
            float4 p1 = h1[d4];
            s0 += w.x * p0.x + w.y * p0.y + w.z * p0.z + w.w * p0.w;
            s1 += w.x * p1.x + w.y * p1.y + w.z * p1.z + w.w * p1.w;
        }

        r0 = tanhf(x0 + s0);
        r1 = tanhf(x1 + s1);
        int nxt = cur ^ 1;
        hb[nxt * 512 + 0 * KK + k] = r0;
        hb[nxt * 512 + 1 * KK + k] = r1;
        cur = nxt;
        __syncthreads();
    }

    out[(size_t)b0 * KK + k] = r0;
    out[(size_t)b1 * KK + k] = r1;
}

// ---------------- launch ----------------
extern "C" void kernel_launch(void* const* d_in, const int* in_sizes, int n_in,
                              void* d_out, int out_size) {
    const float* X = (const float*)d_in[0];   // [B,T,D]
    const float* U = (const float*)d_in[1];   // [D,K]
    const float* W = (const float*)d_in[2];   // [K,K]
    const float* b = (const float*)d_in[3];   // [K]
    float* out = (float*)d_out;               // [B,1,K]

    static int smem_set = -1;
    // idempotent, not a stream op: safe under capture; call every time
    cudaFuncSetAttribute(rnn_rec_kernel,
                         cudaFuncAttributeMaxDynamicSharedMemorySize,
                         SMEM_TOTAL_BYTES);
    (void)smem_set;

    prep_w_kernel<<<KK, 256>>>(W);
    dim3 g1(MM / P1_BM, KK / P1_BN);
    xu_gemm_kernel<<<g1, 256>>>(X, U, b);
    rnn_rec_kernel<<<BB / 2, 256, SMEM_TOTAL_BYTES>>>(out);
}

// round 2
// speedup vs baseline: 1.3520x; 1.3520x over previous
#include <cuda_runtime.h>
#include <cuda_bf16.h>
#include <math.h>

// Problem dims
#define BB 256
#define TT 512
#define DD 256
#define KK 256
#define MM (BB * TT)   // 131072

typedef unsigned long long u64;

// ---------------- f32x2 helpers ----------------
__device__ __forceinline__ u64 ffma2(u64 a, u64 b, u64 c) {
    u64 d;
    asm("fma.rn.f32x2 %0, %1, %2, %3;" : "=l"(d) : "l"(a), "l"(b), "l"(c));
    return d;
}
__device__ __forceinline__ u64 dup2(float x) {
    u64 d;
    asm("mov.b64 %0, {%1, %1};" : "=l"(d) : "f"(x));
    return d;
}
__device__ __forceinline__ float2 unpk2(u64 v) {
    float2 r;
    asm("mov.b64 {%0, %1}, %2;" : "=f"(r.x), "=f"(r.y) : "l"(v));
    return r;
}

// ---------------- scratch (device globals: allowed) ----------------
__device__ float g_xu[(size_t)MM * KK];     // 128 MB: x@U + b
__device__ float g_wt4[DD * KK];            // repacked W: [(d/4)][k][d%4]

// ---------------- phase 0: repack W ----------------
__global__ void prep_w_kernel(const float* __restrict__ W) {
    int i = blockIdx.x * 256 + threadIdx.x;   // 0 .. 65535
    int d = i >> 8;
    int k = i & 255;
    g_wt4[(((d >> 2) * KK + k) << 2) + (d & 3)] = W[i];
}

// ---------------- phase 1: xU = X @ U + b (FFMA2, M-packed) ----------------
#define P1_BM 128
#define P1_BN 64
#define P1_BK 16

__global__ __launch_bounds__(256) void xu_gemm_kernel(
    const float* __restrict__ X,   // [MM, DD]
    const float* __restrict__ U,   // [DD, KK]
    const float* __restrict__ bias // [KK]
) {
    __shared__ float As[P1_BK][P1_BM];   // A stored transposed: [kk][m]
    __shared__ float Bs[P1_BK][P1_BN];

    const int tid = threadIdx.x;
    const int m0 = blockIdx.x * P1_BM;
    const int n0 = blockIdx.y * P1_BN;
    const int tx = tid & 15;   // n dir: 16 * 4 = 64
    const int ty = tid >> 4;   // m dir: 16 * 8 = 128

    // acc2[ip][j]: f32x2 over m-pair (m = ty*8 + 2*ip (+1)), n = n0 + tx*4 + j
    u64 acc2[4][4];
#pragma unroll
    for (int i = 0; i < 4; ++i)
#pragma unroll
        for (int j = 0; j < 4; ++j) acc2[i][j] = 0ULL;

    const int ar = tid >> 2;          // 0..63
    const int ac4 = (tid & 3) << 2;   // 0,4,8,12
    const int br = tid >> 4;          // 0..15
    const int bc4 = (tid & 15) << 2;  // 0..60

    for (int k0 = 0; k0 < DD; k0 += P1_BK) {
        // load A tile 128x16 (2 float4 per thread), store transposed
#pragma unroll
        for (int i = 0; i < 2; ++i) {
            int r = ar + i * 64;
            float4 v = *(const float4*)&X[(size_t)(m0 + r) * DD + k0 + ac4];
            As[ac4 + 0][r] = v.x;
            As[ac4 + 1][r] = v.y;
            As[ac4 + 2][r] = v.z;
            As[ac4 + 3][r] = v.w;
        }
        // load B tile 16x64 (1 float4 per thread)
        {
            float4 v = *(const float4*)&U[(size_t)(k0 + br) * KK + n0 + bc4];
            *(float4*)&Bs[br][bc4] = v;
        }
        __syncthreads();

#pragma unroll
        for (int kk = 0; kk < P1_BK; ++kk) {
            // a: 4 m-pairs as f32x2 (As is m-contiguous)
            ulonglong2 a01 = *(const ulonglong2*)&As[kk][ty * 8 + 0];
            ulonglong2 a23 = *(const ulonglong2*)&As[kk][ty * 8 + 4];
            float4 bv = *(const float4*)&Bs[kk][tx * 4];
            u64 b0 = dup2(bv.x), b1 = dup2(bv.y), b2 = dup2(bv.z), b3 = dup2(bv.w);

            acc2[0][0] = ffma2(a01.x, b0, acc2[0][0]);
            acc2[0][1] = ffma2(a01.x, b1, acc2[0][1]);
            acc2[0][2] = ffma2(a01.x, b2, acc2[0][2]);
            acc2[0][3] = ffma2(a01.x, b3, acc2[0][3]);
            acc2[1][0] = ffma2(a01.y, b0, acc2[1][0]);
            acc2[1][1] = ffma2(a01.y, b1, acc2[1][1]);
            acc2[1][2] = ffma2(a01.y, b2, acc2[1][2]);
            acc2[1][3] = ffma2(a01.y, b3, acc2[1][3]);
            acc2[2][0] = ffma2(a23.x, b0, acc2[2][0]);
            acc2[2][1] = ffma2(a23.x, b1, acc2[2][1]);
            acc2[2][2] = ffma2(a23.x, b2, acc2[2][2]);
            acc2[2][3] = ffma2(a23.x, b3, acc2[2][3]);
            acc2[3][0] = ffma2(a23.y, b0, acc2[3][0]);
            acc2[3][1] = ffma2(a23.y, b1, acc2[3][1]);
            acc2[3][2] = ffma2(a23.y, b2, acc2[3][2]);
            acc2[3][3] = ffma2(a23.y, b3, acc2[3][3]);
        }
        __syncthreads();
    }

    // epilogue: add bias, write (even/odd m rows per pair)
    float4 bv = *(const float4*)&bias[n0 + tx * 4];
#pragma unroll
    for (int ip = 0; ip < 4; ++ip) {
        float2 v0 = unpk2(acc2[ip][0]);
        float2 v1 = unpk2(acc2[ip][1]);
        float2 v2 = unpk2(acc2[ip][2]);
        float2 v3 = unpk2(acc2[ip][3]);
        int me = m0 + ty * 8 + 2 * ip;
        float4 oe, oo;
        oe.x = v0.x + bv.x; oe.y = v1.x + bv.y; oe.z = v2.x + bv.z; oe.w = v3.x + bv.w;
        oo.x = v0.y + bv.x; oo.y = v1.y + bv.y; oo.z = v2.y + bv.z; oo.w = v3.y + bv.w;
        *(float4*)&g_xu[(size_t)me * KK + n0 + tx * 4] = oe;
        *(float4*)&g_xu[(size_t)(me + 1) * KK + n0 + tx * 4] = oo;
    }
}

// ---------------- phase 2: recurrence (FFMA2, W in regs + smem) ----------------
// 128 blocks x 256 threads; block owns 2 batch rows. Thread k owns output col k.
// W column k: d in [0, RD) held in registers (loop-invariant), d in [RD, 256)
// staged in SMEM. Zero per-step L2/DRAM W traffic.
#define RD 144
#define RD4 (RD / 4)            // 36
#define SD (DD - RD)            // 112
#define SD4 (SD / 4)            // 28
#define WS_FLOATS (SD4 * KK * 4)                 // 28672 floats = 114688 B
#define HB_FLOATS (2 * 2 * KK)                   // 1024 floats
#define REC_SMEM_BYTES ((WS_FLOATS + HB_FLOATS) * 4)   // 118784 B

__global__ __launch_bounds__(256, 1) void rnn_rec_kernel(float* __restrict__ out) {
    extern __shared__ float smem[];
    float* ws = smem;                       // [SD4*KK] float4-groups (flat floats)
    float* hb = smem + WS_FLOATS;           // h[buf][row][k]

    const int k = threadIdx.x;
    const int b0 = blockIdx.x * 2;
    const int b1 = b0 + 1;

    // load register-resident W column part (d = 0..RD-1), f32x2 pairs
    u64 wreg[RD4 * 2];
#pragma unroll
    for (int r4 = 0; r4 < RD4; ++r4) {
        ulonglong2 v = *(const ulonglong2*)&g_wt4[((size_t)r4 * KK + k) << 2];
        wreg[2 * r4 + 0] = v.x;
        wreg[2 * r4 + 1] = v.y;
    }

    // stage SMEM part of W (d = RD..255), same float4-of-4-d layout
    {
        const float4* src = (const float4*)&g_wt4[(size_t)RD4 * KK * 4];
        float4* dst = (float4*)ws;
        for (int i = k; i < SD4 * KK; i += 256) dst[i] = src[i];
    }

    const float* xu0 = g_xu + (size_t)b0 * TT * KK + k;
    const float* xu1 = g_xu + (size_t)b1 * TT * KK + k;

    // t = 0 : h = tanh(xu_0)
    float a0 = xu0[0];
    float a1 = xu1[0];
    __syncthreads();          // ws staged, h buffers safe to write
    int cur = 0;
    hb[cur * 512 + 0 * KK + k] = tanhf(a0);
    hb[cur * 512 + 1 * KK + k] = tanhf(a1);
    __syncthreads();

    float r0 = 0.f, r1 = 0.f;
    for (int t = 1; t < TT; ++t) {
        float x0 = xu0[(size_t)t * KK];   // long-latency, consumed at tanh
        float x1 = xu1[(size_t)t * KK];
        const float* hc0 = hb + cur * 512;
        const float* hc1 = hb + cur * 512 + KK;

        u64 a0A = 0ULL, a0B = 0ULL, a1A = 0ULL, a1B = 0ULL;

        // register-W part
#pragma unroll
        for (int r4 = 0; r4 < RD4; ++r4) {
            ulonglong2 h0v = *(const ulonglong2*)(hc0 + r4 * 4);
            ulonglong2 h1v = *(const ulonglong2*)(hc1 + r4 * 4);
            a0A = ffma2(wreg[2 * r4 + 0], h0v.x, a0A);
            a0B = ffma2(wreg[2 * r4 + 1], h0v.y, a0B);
            a1A = ffma2(wreg[2 * r4 + 0], h1v.x, a1A);
            a1B = ffma2(wreg[2 * r4 + 1], h1v.y, a1B);
        }
        // SMEM-W part
#pragma unroll
        for (int s4 = 0; s4 < SD4; ++s4) {
            ulonglong2 wv = *(const ulonglong2*)(ws + (((size_t)s4 * KK + k) << 2));
            ulonglong2 h0v = *(const ulonglong2*)(hc0 + RD + s4 * 4);
            ulonglong2 h1v = *(const ulonglong2*)(hc1 + RD + s4 * 4);
            a0A = ffma2(wv.x, h0v.x, a0A);
            a0B = ffma2(wv.y, h0v.y, a0B);
            a1A = ffma2(wv.x, h1v.x, a1A);
            a1B = ffma2(wv.y, h1v.y, a1B);
        }

        float2 pA = unpk2(a0A), pB = unpk2(a0B);
        float2 qA = unpk2(a1A), qB = unpk2(a1B);
        float s0 = (pA.x + pA.y) + (pB.x + pB.y);
        float s1 = (qA.x + qA.y) + (qB.x + qB.y);

        r0 = tanhf(x0 + s0);
        r1 = tanhf(x1 + s1);
        int nxt = cur ^ 1;
        hb[nxt * 512 + 0 * KK + k] = r0;
        hb[nxt * 512 + 1 * KK + k] = r1;
        cur = nxt;
        __syncthreads();
    }

    out[(size_t)b0 * KK + k] = r0;
    out[(size_t)b1 * KK + k] = r1;
}

// ---------------- launch ----------------
extern "C" void kernel_launch(void* const* d_in, const int* in_sizes, int n_in,
                              void* d_out, int out_size) {
    const float* X = (const float*)d_in[0];   // [B,T,D]
    const float* U = (const float*)d_in[1];   // [D,K]
    const float* W = (const float*)d_in[2];   // [K,K]
    const float* b = (const float*)d_in[3];   // [K]
    float* out = (float*)d_out;               // [B,1,K]

    // idempotent, not a stream op: safe under capture
    cudaFuncSetAttribute(rnn_rec_kernel,
                         cudaFuncAttributeMaxDynamicSharedMemorySize,
                         REC_SMEM_BYTES);

    prep_w_kernel<<<KK, 256>>>(W);
    dim3 g1(MM / P1_BM, KK / P1_BN);
    xu_gemm_kernel<<<g1, 256>>>(X, U, b);
    rnn_rec_kernel<<<BB / 2, 256, REC_SMEM_BYTES>>>(out);
}